// round 13
// baseline (speedup 1.0000x reference)
#include <cuda_runtime.h>
#include <math.h>
#include <stdint.h>

// Problem constants
#define V 50000
#define E 300
#define H 2048
#define L 512
#define CAT (E + H)          // 2348
#define CAT4 (CAT / 4)       // 587  float4 per row
#define H4 (H / 4)           // 512  float4 per row
#define G3H (3 * H)          // 6144

// k_out_gemv launch geometry (needed for partial-array sizing)
#define OUT_BLOCKS 1184      // 148 SMs * 8
#define OUT_WARPS  (OUT_BLOCKS * 8)   // 9472 (blockDim 256 -> 8 warps)

// attn_applied split
#define AA_NY 16
#define AA_CHUNK (L / AA_NY) // 32

// ---------------- device scratch (allocation-free) ----------------
__device__ __align__(16) float g_cat1[CAT];        // [embedded | h0]
__device__ __align__(16) float g_cat2[CAT];        // [embedded | attn_applied]
__device__ float g_attn_logits[L];
__device__ float g_attn_w[L];
__device__ float g_ap[AA_NY * H];                  // attn_applied partials
__device__ __align__(16) float g_x[H];             // relu(comb) output
__device__ float g_gg[2 * G3H];                    // [gi(6144) | gh(6144)]
__device__ __align__(16) float g_hnew[H];
__device__ float g_logits[V];
__device__ float g_pm[OUT_WARPS];
__device__ float g_ps[OUT_WARPS];
__device__ float g_lse;

// ---------------- K0: build cat1 and embedded part of cat2 ----------------
__global__ void k_setup(const int* __restrict__ input,
                        const float* __restrict__ hidden,
                        const float* __restrict__ emb) {
    int i = blockIdx.x * blockDim.x + threadIdx.x;
    if (i < E) {
        float e = emb[(long)input[0] * E + i];
        g_cat1[i] = e;
        g_cat2[i] = e;
    } else if (i < CAT) {
        g_cat1[i] = hidden[i - E];
    }
}

// ---------------- generic warp-per-row GEMV over 2348-wide rows -----------
// MODE 0: x = g_cat1, y = g_attn_logits, no activation   (attn logits)
// MODE 1: x = g_cat2, y = g_x, relu                      (combine layer)
template <int MODE>
__global__ void k_gemv2348(const float4* __restrict__ W4,
                           const float* __restrict__ b, int rows) {
    const float4* x4 = (MODE == 0) ? (const float4*)g_cat1 : (const float4*)g_cat2;
    float* y         = (MODE == 0) ? g_attn_logits : g_x;

    int gt   = blockIdx.x * blockDim.x + threadIdx.x;
    int warp = gt >> 5;
    int lane = gt & 31;
    if (warp >= rows) return;

    const float4* Wr = W4 + (size_t)warp * CAT4;
    float acc = 0.f;
#pragma unroll
    for (int k = 0; k < 19; ++k) {
        int idx = k * 32 + lane;
        if (idx < CAT4) {
            float4 w  = Wr[idx];
            float4 xv = x4[idx];
            acc += w.x * xv.x + w.y * xv.y + w.z * xv.z + w.w * xv.w;
        }
    }
#pragma unroll
    for (int o = 16; o; o >>= 1) acc += __shfl_down_sync(0xffffffffu, acc, o);
    if (lane == 0) {
        float v = acc + b[warp];
        if (MODE == 1) v = fmaxf(v, 0.f);
        y[warp] = v;
    }
}

// ---------------- K2: softmax over 512 attn logits (1 block, 512 thr) -----
__global__ void k_softmax512(float* __restrict__ out_attn) {
    int t = threadIdx.x, lane = t & 31, w = t >> 5;   // 16 warps
    __shared__ float red[16];
    __shared__ float bc[2];

    float v = g_attn_logits[t];

    // block max
    float m = v;
#pragma unroll
    for (int o = 16; o; o >>= 1) m = fmaxf(m, __shfl_xor_sync(0xffffffffu, m, o));
    if (lane == 0) red[w] = m;
    __syncthreads();
    if (w == 0) {
        float mm = (lane < 16) ? red[lane] : -INFINITY;
#pragma unroll
        for (int o = 16; o; o >>= 1) mm = fmaxf(mm, __shfl_xor_sync(0xffffffffu, mm, o));
        if (lane == 0) bc[0] = mm;
    }
    __syncthreads();
    float M = bc[0];

    // block sum of exp
    float p = expf(v - M);
    float s = p;
#pragma unroll
    for (int o = 16; o; o >>= 1) s += __shfl_xor_sync(0xffffffffu, s, o);
    if (lane == 0) red[w] = s;
    __syncthreads();
    if (w == 0) {
        float ss = (lane < 16) ? red[lane] : 0.f;
#pragma unroll
        for (int o = 16; o; o >>= 1) ss += __shfl_xor_sync(0xffffffffu, ss, o);
        if (lane == 0) bc[1] = ss;
    }
    __syncthreads();

    float wgt = p / bc[1];
    g_attn_w[t]  = wgt;
    out_attn[t]  = wgt;
}

// ---------------- K3: attn_applied partials: w @ encoder_outputs ----------
// grid (H/256, AA_NY), block 256. Each y-block reduces a 32-row chunk.
__global__ void k_attn_apply(const float* __restrict__ enc) {
    __shared__ float w[AA_CHUNK];
    int l0 = blockIdx.y * AA_CHUNK;
    if (threadIdx.x < AA_CHUNK) w[threadIdx.x] = g_attn_w[l0 + threadIdx.x];
    __syncthreads();

    int col = blockIdx.x * 256 + threadIdx.x;
    const float* e = enc + (size_t)l0 * H + col;
    float acc = 0.f;
#pragma unroll
    for (int l = 0; l < AA_CHUNK; ++l) acc += w[l] * e[(size_t)l * H];
    g_ap[blockIdx.y * H + col] = acc;
}

// ---------------- K3b: sum partials into g_cat2[300..] --------------------
__global__ void k_attn_reduce() {
    int col = blockIdx.x * 256 + threadIdx.x;
    float a = 0.f;
#pragma unroll
    for (int c = 0; c < AA_NY; ++c) a += g_ap[c * H + col];
    g_cat2[E + col] = a;
}

// ---------------- K5: GRU input/hidden GEMVs (12288 warp-rows of 2048) ----
__global__ void k_gru_gemv(const float4* __restrict__ Wih4,
                           const float4* __restrict__ Whh4,
                           const float* __restrict__ bih,
                           const float* __restrict__ bhh,
                           const float4* __restrict__ h04) {
    int gt   = blockIdx.x * blockDim.x + threadIdx.x;
    int warp = gt >> 5;
    int lane = gt & 31;
    if (warp >= 2 * G3H) return;

    const float4* Wr;
    const float4* xv;
    const float*  b;
    int rr;
    if (warp < G3H) { rr = warp;        Wr = Wih4 + (size_t)rr * H4; xv = (const float4*)g_x; b = bih; }
    else            { rr = warp - G3H;  Wr = Whh4 + (size_t)rr * H4; xv = h04;                b = bhh; }

    float acc = 0.f;
#pragma unroll
    for (int k = 0; k < 16; ++k) {
        int idx = k * 32 + lane;
        float4 w = Wr[idx];
        float4 x = xv[idx];
        acc += w.x * x.x + w.y * x.y + w.z * x.z + w.w * x.w;
    }
#pragma unroll
    for (int o = 16; o; o >>= 1) acc += __shfl_down_sync(0xffffffffu, acc, o);
    if (lane == 0) g_gg[warp] = acc + b[rr];
}

// ---------------- K6: GRU gate math -> h_new ------------------------------
__global__ void k_gates(const float* __restrict__ hidden, float* __restrict__ out_h) {
    int j = blockIdx.x * 256 + threadIdx.x;
    float i_r = g_gg[j],          i_z = g_gg[H + j],        i_n = g_gg[2 * H + j];
    float h_r = g_gg[G3H + j],    h_z = g_gg[G3H + H + j],  h_n = g_gg[G3H + 2 * H + j];
    float r = 1.f / (1.f + expf(-(i_r + h_r)));
    float z = 1.f / (1.f + expf(-(i_z + h_z)));
    float n = tanhf(i_n + r * h_n);
    float h = (1.f - z) * n + z * hidden[j];
    g_hnew[j] = h;
    out_h[j]  = h;
}

// ---------------- K7: output GEMV (50000 x 2048) + fused LSE partials -----
__global__ void k_out_gemv(const float4* __restrict__ W4,
                           const float* __restrict__ bias) {
    const float4* x4 = (const float4*)g_hnew;
    int gt   = blockIdx.x * blockDim.x + threadIdx.x;
    int gw   = gt >> 5;
    int lane = gt & 31;
    int nw   = (gridDim.x * blockDim.x) >> 5;

    float m = -INFINITY, s = 0.f;
    for (int r = gw; r < V; r += nw) {
        const float4* Wr = W4 + (size_t)r * H4;
        float acc = 0.f;
#pragma unroll
        for (int k = 0; k < 16; ++k) {
            int idx = k * 32 + lane;
            float4 w = Wr[idx];
            float4 x = x4[idx];
            acc += w.x * x.x + w.y * x.y + w.z * x.z + w.w * x.w;
        }
#pragma unroll
        for (int o = 16; o; o >>= 1) acc += __shfl_down_sync(0xffffffffu, acc, o);
        if (lane == 0) {
            float v = acc + bias[r];
            g_logits[r] = v;
            float mn = fmaxf(m, v);
            s = s * expf(m - mn) + expf(v - mn);
            m = mn;
        }
    }
    if (lane == 0) { g_pm[gw] = m; g_ps[gw] = s; }
}

// ---------------- K8: merge per-warp (m,s) partials -> g_lse --------------
__global__ void k_lse_reduce() {
    int t = threadIdx.x, lane = t & 31, w = t >> 5;  // 32 warps of 1024
    float m = -INFINITY, s = 0.f;
    for (int i = t; i < OUT_WARPS; i += 1024) {
        float m2 = g_pm[i], s2 = g_ps[i];
        float M = fmaxf(m, m2);
        s = s * expf(m - M) + s2 * expf(m2 - M);
        m = M;
    }
#pragma unroll
    for (int o = 16; o; o >>= 1) {
        float m2 = __shfl_xor_sync(0xffffffffu, m, o);
        float s2 = __shfl_xor_sync(0xffffffffu, s, o);
        float M = fmaxf(m, m2);
        s = s * expf(m - M) + s2 * expf(m2 - M);
        m = M;
    }
    __shared__ float sm[32], ss[32];
    if (lane == 0) { sm[w] = m; ss[w] = s; }
    __syncthreads();
    if (w == 0) {
        m = sm[lane]; s = ss[lane];
#pragma unroll
        for (int o = 16; o; o >>= 1) {
            float m2 = __shfl_xor_sync(0xffffffffu, m, o);
            float s2 = __shfl_xor_sync(0xffffffffu, s, o);
            float M = fmaxf(m, m2);
            s = s * expf(m - M) + s2 * expf(m2 - M);
            m = M;
        }
        if (lane == 0) g_lse = m + logf(s);
    }
}

// ---------------- K9: log_softmax finalize --------------------------------
__global__ void k_finalize(float* __restrict__ out) {
    int i = blockIdx.x * 256 + threadIdx.x;
    if (i < V) out[i] = g_logits[i] - g_lse;
}

// ---------------- launcher -------------------------------------------------
extern "C" void kernel_launch(void* const* d_in, const int* in_sizes, int n_in,
                              void* d_out, int out_size) {
    const int*   input  = (const int*)  d_in[0];
    const float* hidden = (const float*)d_in[1];
    const float* enc    = (const float*)d_in[2];
    const float* emb    = (const float*)d_in[3];
    const float* attn_W = (const float*)d_in[4];
    const float* attn_b = (const float*)d_in[5];
    const float* comb_W = (const float*)d_in[6];
    const float* comb_b = (const float*)d_in[7];
    const float* W_ih   = (const float*)d_in[8];
    const float* W_hh   = (const float*)d_in[9];
    const float* b_ih   = (const float*)d_in[10];
    const float* b_hh   = (const float*)d_in[11];
    const float* out_W  = (const float*)d_in[12];
    const float* out_b  = (const float*)d_in[13];

    float* out = (float*)d_out;
    // output layout: [log_softmax (V)] [h_new (H)] [attn_weights (L)]
    float* out_logp = out;
    float* out_h    = out + V;
    float* out_attn = out + V + H;

    // 1. build cat1 = [embedded | h0], seed cat2 with embedded
    k_setup<<<(CAT + 255) / 256, 256>>>(input, hidden, emb);

    // 2. attention logits: 512 warp-rows, small blocks to spread across SMs
    k_gemv2348<0><<<(L * 32 + 63) / 64, 64>>>((const float4*)attn_W, attn_b, L);

    // 3. softmax over 512
    k_softmax512<<<1, 512>>>(out_attn);

    // 4. attn_applied = attn_w @ encoder_outputs (partials + reduce)
    k_attn_apply<<<dim3(H / 256, AA_NY), 256>>>(enc);
    k_attn_reduce<<<H / 256, 256>>>();

    // 5. combine + relu: 2048 warp-rows of 2348
    k_gemv2348<1><<<(H * 32 + 255) / 256, 256>>>((const float4*)comb_W, comb_b, H);

    // 6. GRU gate GEMVs: 12288 warp-rows of 2048
    k_gru_gemv<<<(2 * G3H * 32 + 255) / 256, 256>>>(
        (const float4*)W_ih, (const float4*)W_hh, b_ih, b_hh, (const float4*)hidden);

    // 7. GRU gate math -> h_new
    k_gates<<<H / 256, 256>>>(hidden, out_h);

    // 8. output GEMV 50000x2048 with fused online log-sum-exp partials
    k_out_gemv<<<OUT_BLOCKS, 256>>>((const float4*)out_W, out_b);

    // 9. merge partials -> lse, then finalize log_softmax
    k_lse_reduce<<<1, 1024>>>();
    k_finalize<<<(V + 255) / 256, 256>>>(out_logp);
}

// round 14
// speedup vs baseline: 1.1778x; 1.1778x over previous
#include <cuda_runtime.h>
#include <math.h>
#include <stdint.h>

// Problem constants
#define V 50000
#define E 300
#define H 2048
#define L 512
#define CAT (E + H)          // 2348
#define CAT4 587             // float4 per 2348-row
#define H4 512               // float4 per 2048-row
#define G3H (3 * H)          // 6144

// Launch geometry: 2 CTAs per SM on 148 SMs -> all blocks resident (safe grid barrier)
#define NB 296
#define NT 256
#define NWARP ((NB * NT) / 32)   // 2368

#define AA_NY 16
#define AA_CHUNK (L / AA_NY)     // 32

// ---------------- device scratch (allocation-free) ----------------
__device__ __align__(16) float g_cat1[CAT];   // [embedded | h0]
__device__ __align__(16) float g_cat2[CAT];   // [embedded | attn_applied]
__device__ float g_attn_logits[L];
__device__ float g_attn_w[L];
__device__ float g_ap[AA_NY * H];
__device__ __align__(16) float g_x[H];
__device__ float g_gh[G3H];
__device__ float g_gi[G3H];
__device__ __align__(16) float g_hnew[H];
__device__ float g_logits[V];
__device__ float g_pm[NB];
__device__ float g_ps[NB];
__device__ unsigned int g_bar;                // monotone ticket counter (replay-safe)

// ---------------- grid-wide barrier (all NB blocks resident) ----------------
__device__ __forceinline__ void grid_bar() {
    __syncthreads();
    __threadfence();
    if (threadIdx.x == 0) {
        unsigned int t = atomicAdd(&g_bar, 1u) + 1u;
        unsigned int target = ((t + NB - 1u) / NB) * NB;
        while (atomicAdd(&g_bar, 0u) < target) { __nanosleep(64); }
        __threadfence();
    }
    __syncthreads();
}

__device__ __forceinline__ float warp_sum(float a) {
#pragma unroll
    for (int o = 16; o; o >>= 1) a += __shfl_down_sync(0xffffffffu, a, o);
    return a;
}

__global__ void __launch_bounds__(NT, 2)
fused_decoder(const int* __restrict__ input,
              const float* __restrict__ hidden,
              const float* __restrict__ enc,
              const float* __restrict__ emb,
              const float4* __restrict__ attn_W4,
              const float* __restrict__ attn_b,
              const float4* __restrict__ comb_W4,
              const float* __restrict__ comb_b,
              const float4* __restrict__ Wih4,
              const float4* __restrict__ Whh4,
              const float* __restrict__ b_ih,
              const float* __restrict__ b_hh,
              const float4* __restrict__ outW4,
              const float* __restrict__ out_b,
              float* __restrict__ out_logp,
              float* __restrict__ out_h,
              float* __restrict__ out_attn) {
    __shared__ float sA[32];
    __shared__ float sB[32];
    __shared__ float s_bcast;

    const int tid  = threadIdx.x;
    const int lane = tid & 31;
    const int wid  = tid >> 5;
    const int gt   = blockIdx.x * NT + tid;
    const int gw   = gt >> 5;
    const float4* h04 = (const float4*)hidden;

    // ---- S0: cat1 = [embedded | h0], cat2[0..E) = embedded ----
    if (gt < CAT) {
        if (gt < E) {
            float e = emb[(long)input[0] * E + gt];
            g_cat1[gt] = e;
            g_cat2[gt] = e;
        } else {
            g_cat1[gt] = hidden[gt - E];
        }
    }
    grid_bar();

    // ---- S1: attention logits (512 rows x 2348)  +  gh = W_hh @ h0 (6144 rows x 2048) ----
    for (int w = gw; w < L + G3H; w += NWARP) {
        float acc = 0.f;
        if (w < L) {
            const float4* Wr = attn_W4 + (size_t)w * CAT4;
            const float4* x4 = (const float4*)g_cat1;
#pragma unroll
            for (int k = 0; k < 19; ++k) {
                int idx = k * 32 + lane;
                if (idx < CAT4) {
                    float4 a = Wr[idx], b = x4[idx];
                    acc += a.x * b.x + a.y * b.y + a.z * b.z + a.w * b.w;
                }
            }
            acc = warp_sum(acc);
            if (lane == 0) g_attn_logits[w] = acc + attn_b[w];
        } else {
            int r = w - L;
            const float4* Wr = Whh4 + (size_t)r * H4;
#pragma unroll
            for (int k = 0; k < 16; ++k) {
                int idx = k * 32 + lane;
                float4 a = Wr[idx], b = h04[idx];
                acc += a.x * b.x + a.y * b.y + a.z * b.z + a.w * b.w;
            }
            acc = warp_sum(acc);
            if (lane == 0) g_gh[r] = acc + b_hh[r];
        }
    }
    grid_bar();

    // ---- S2: softmax over 512 attn logits (block 0 only, 2 elems/thread) ----
    if (blockIdx.x == 0) {
        float v0 = g_attn_logits[tid];
        float v1 = g_attn_logits[tid + 256];
        float m = fmaxf(v0, v1);
#pragma unroll
        for (int o = 16; o; o >>= 1) m = fmaxf(m, __shfl_xor_sync(0xffffffffu, m, o));
        if (lane == 0) sA[wid] = m;
        __syncthreads();
        if (wid == 0) {
            float mm = (lane < 8) ? sA[lane] : -INFINITY;
#pragma unroll
            for (int o = 4; o; o >>= 1) mm = fmaxf(mm, __shfl_xor_sync(0xffffffffu, mm, o));
            if (lane == 0) s_bcast = mm;
        }
        __syncthreads();
        float M = s_bcast;
        float p0 = expf(v0 - M), p1 = expf(v1 - M);
        float s = warp_sum(p0 + p1);
        if (lane == 0) sA[wid] = s;
        __syncthreads();
        if (wid == 0) {
            float ss = (lane < 8) ? sA[lane] : 0.f;
#pragma unroll
            for (int o = 4; o; o >>= 1) ss += __shfl_xor_sync(0xffffffffu, ss, o);
            if (lane == 0) s_bcast = ss;
        }
        __syncthreads();
        float inv = 1.f / s_bcast;
        float w0 = p0 * inv, w1 = p1 * inv;
        g_attn_w[tid] = w0;       g_attn_w[tid + 256] = w1;
        out_attn[tid] = w0;       out_attn[tid + 256] = w1;
    }
    grid_bar();

    // ---- S3: attn_applied partials: 16 chunks x 2048 cols ----
    if (gt < AA_NY * H) {
        int col = gt & (H - 1);
        int chunk = gt >> 11;
        int l0 = chunk * AA_CHUNK;
        const float* e = enc + (size_t)l0 * H + col;
        float acc = 0.f;
#pragma unroll
        for (int l = 0; l < AA_CHUNK; ++l) acc += g_attn_w[l0 + l] * e[(size_t)l * H];
        g_ap[chunk * H + col] = acc;
    }
    grid_bar();

    // ---- S4: reduce partials into cat2[E..) ----
    if (gt < H) {
        float a = 0.f;
#pragma unroll
        for (int c = 0; c < AA_NY; ++c) a += g_ap[c * H + gt];
        g_cat2[E + gt] = a;
    }
    grid_bar();

    // ---- S5: combine + relu: 2048 rows x 2348 ----
    for (int w = gw; w < H; w += NWARP) {
        const float4* Wr = comb_W4 + (size_t)w * CAT4;
        const float4* x4 = (const float4*)g_cat2;
        float acc = 0.f;
#pragma unroll
        for (int k = 0; k < 19; ++k) {
            int idx = k * 32 + lane;
            if (idx < CAT4) {
                float4 a = Wr[idx], b = x4[idx];
                acc += a.x * b.x + a.y * b.y + a.z * b.z + a.w * b.w;
            }
        }
        acc = warp_sum(acc);
        if (lane == 0) g_x[w] = fmaxf(acc + comb_b[w], 0.f);
    }
    grid_bar();

    // ---- S6: gi = W_ih @ x : 6144 rows x 2048 ----
    for (int w = gw; w < G3H; w += NWARP) {
        const float4* Wr = Wih4 + (size_t)w * H4;
        const float4* x4 = (const float4*)g_x;
        float acc = 0.f;
#pragma unroll
        for (int k = 0; k < 16; ++k) {
            int idx = k * 32 + lane;
            float4 a = Wr[idx], b = x4[idx];
            acc += a.x * b.x + a.y * b.y + a.z * b.z + a.w * b.w;
        }
        acc = warp_sum(acc);
        if (lane == 0) g_gi[w] = acc + b_ih[w];
    }
    grid_bar();

    // ---- S7: GRU gates -> h_new ----
    if (gt < H) {
        float i_r = g_gi[gt],       i_z = g_gi[H + gt],       i_n = g_gi[2 * H + gt];
        float h_r = g_gh[gt],       h_z = g_gh[H + gt],       h_n = g_gh[2 * H + gt];
        float r = 1.f / (1.f + expf(-(i_r + h_r)));
        float z = 1.f / (1.f + expf(-(i_z + h_z)));
        float n = tanhf(i_n + r * h_n);
        float h = (1.f - z) * n + z * hidden[gt];
        g_hnew[gt] = h;
        out_h[gt]  = h;
    }
    grid_bar();

    // ---- S8: output GEMV 50000 x 2048 with fused online log-sum-exp ----
    {
        const float4* x4 = (const float4*)g_hnew;
        float m = -INFINITY, s = 0.f;
        for (int r = gw; r < V; r += NWARP) {
            const float4* Wr = outW4 + (size_t)r * H4;
            float acc = 0.f;
#pragma unroll
            for (int k = 0; k < 16; ++k) {
                int idx = k * 32 + lane;
                float4 a = Wr[idx], b = x4[idx];
                acc += a.x * b.x + a.y * b.y + a.z * b.z + a.w * b.w;
            }
            acc = warp_sum(acc);
            if (lane == 0) {
                float v = acc + out_b[r];
                g_logits[r] = v;
                float mn = fmaxf(m, v);
                s = s * expf(m - mn) + expf(v - mn);
                m = mn;
            }
        }
        // merge 8 warps -> per-block (m,s)
        if (lane == 0) { sA[wid] = m; sB[wid] = s; }
        __syncthreads();
        if (tid == 0) {
            float M = sA[0], S = sB[0];
#pragma unroll
            for (int i = 1; i < 8; ++i) {
                float m2 = sA[i], s2 = sB[i];
                float MM = fmaxf(M, m2);
                S = S * expf(M - MM) + s2 * expf(m2 - MM);
                M = MM;
            }
            g_pm[blockIdx.x] = M;
            g_ps[blockIdx.x] = S;
        }
    }
    grid_bar();

    // ---- S9: every block reduces the 296 (m,s) partials, then finalizes its slice ----
    {
        float m = -INFINITY, s = 0.f;
        for (int i = tid; i < NB; i += NT) {
            float m2 = g_pm[i], s2 = g_ps[i];
            float M = fmaxf(m, m2);
            s = s * expf(m - M) + s2 * expf(m2 - M);
            m = M;
        }
#pragma unroll
        for (int o = 16; o; o >>= 1) {
            float m2 = __shfl_xor_sync(0xffffffffu, m, o);
            float s2 = __shfl_xor_sync(0xffffffffu, s, o);
            float M = fmaxf(m, m2);
            s = s * expf(m - M) + s2 * expf(m2 - M);
            m = M;
        }
        if (lane == 0) { sA[wid] = m; sB[wid] = s; }
        __syncthreads();
        if (tid == 0) {
            float M = sA[0], S = sB[0];
#pragma unroll
            for (int i = 1; i < 8; ++i) {
                float m2 = sA[i], s2 = sB[i];
                float MM = fmaxf(M, m2);
                S = S * expf(M - MM) + s2 * expf(m2 - MM);
                M = MM;
            }
            s_bcast = M + logf(S);
        }
        __syncthreads();
        float lse = s_bcast;
        if (gt < V) out_logp[gt] = g_logits[gt] - lse;  // NB*NT = 75776 > V
    }
}

// ---------------- launcher: ONE graph node ----------------
extern "C" void kernel_launch(void* const* d_in, const int* in_sizes, int n_in,
                              void* d_out, int out_size) {
    const int*   input  = (const int*)  d_in[0];
    const float* hidden = (const float*)d_in[1];
    const float* enc    = (const float*)d_in[2];
    const float* emb    = (const float*)d_in[3];
    const float* attn_W = (const float*)d_in[4];
    const float* attn_b = (const float*)d_in[5];
    const float* comb_W = (const float*)d_in[6];
    const float* comb_b = (const float*)d_in[7];
    const float* W_ih   = (const float*)d_in[8];
    const float* W_hh   = (const float*)d_in[9];
    const float* b_ih   = (const float*)d_in[10];
    const float* b_hh   = (const float*)d_in[11];
    const float* out_W  = (const float*)d_in[12];
    const float* out_b  = (const float*)d_in[13];

    float* out = (float*)d_out;
    float* out_logp = out;           // [V]
    float* out_h    = out + V;       // [H]
    float* out_attn = out + V + H;   // [L]

    fused_decoder<<<NB, NT>>>(input, hidden, enc, emb,
                              (const float4*)attn_W, attn_b,
                              (const float4*)comb_W, comb_b,
                              (const float4*)W_ih, (const float4*)W_hh,
                              b_ih, b_hh,
                              (const float4*)out_W, out_b,
                              out_logp, out_h, out_attn);
}

// round 15
// speedup vs baseline: 1.1782x; 1.0003x over previous
#include <cuda_runtime.h>
#include <math.h>
#include <stdint.h>

// Problem constants
#define V 50000
#define E 300
#define H 2048
#define L 512
#define CAT (E + H)          // 2348
#define CAT4 587             // float4 per 2348-row
#define H4 512               // float4 per 2048-row
#define G3H (3 * H)          // 6144

// Launch geometry: 2 CTAs per SM on 148 SMs -> all blocks resident (safe grid barrier)
#define NB 296
#define NT 256
#define NWARP ((NB * NT) / 32)   // 2368

#define AA_NY 16
#define AA_CHUNK (L / AA_NY)     // 32

// ---------------- device scratch (allocation-free) ----------------
__device__ __align__(16) float g_cat1[CAT];   // [embedded | h0]
__device__ __align__(16) float g_cat2[CAT];   // [embedded | attn_applied]
__device__ float g_attn_logits[L];
__device__ float g_attn_w[L];
__device__ float g_ap[AA_NY * H];
__device__ __align__(16) float g_x[H];
__device__ float g_gh[G3H];
__device__ float g_gi[G3H];
__device__ __align__(16) float g_hnew[H];
__device__ float g_logits[V];
__device__ float g_pm[NB];
__device__ float g_ps[NB];
__device__ unsigned int g_bar;                // monotone ticket counter (replay-safe)

// ---------------- grid-wide barrier (all NB blocks resident) ----------------
__device__ __forceinline__ void grid_bar() {
    __syncthreads();
    __threadfence();
    if (threadIdx.x == 0) {
        unsigned int t = atomicAdd(&g_bar, 1u) + 1u;
        unsigned int target = ((t + NB - 1u) / NB) * NB;
        while (atomicAdd(&g_bar, 0u) < target) { __nanosleep(64); }
        __threadfence();
    }
    __syncthreads();
}

__device__ __forceinline__ float warp_sum(float a) {
#pragma unroll
    for (int o = 16; o; o >>= 1) a += __shfl_down_sync(0xffffffffu, a, o);
    return a;
}

__global__ void __launch_bounds__(NT, 2)
fused_decoder(const int* __restrict__ input,
              const float* __restrict__ hidden,
              const float* __restrict__ enc,
              const float* __restrict__ emb,
              const float4* __restrict__ attn_W4,
              const float* __restrict__ attn_b,
              const float4* __restrict__ comb_W4,
              const float* __restrict__ comb_b,
              const float4* __restrict__ Wih4,
              const float4* __restrict__ Whh4,
              const float* __restrict__ b_ih,
              const float* __restrict__ b_hh,
              const float4* __restrict__ outW4,
              const float* __restrict__ out_b,
              float* __restrict__ out_logp,
              float* __restrict__ out_h,
              float* __restrict__ out_attn) {
    __shared__ float sA[32];
    __shared__ float sB[32];
    __shared__ float s_bcast;

    const int tid  = threadIdx.x;
    const int lane = tid & 31;
    const int wid  = tid >> 5;
    const int gt   = blockIdx.x * NT + tid;
    const int gw   = gt >> 5;
    const float4* h04 = (const float4*)hidden;

    // ---- S0: cat1 = [embedded | h0], cat2[0..E) = embedded ----
    if (gt < CAT) {
        if (gt < E) {
            float e = emb[(long)input[0] * E + gt];
            g_cat1[gt] = e;
            g_cat2[gt] = e;
        } else {
            g_cat1[gt] = hidden[gt - E];
        }
    }
    grid_bar();

    // ---- S1: attention logits (512 rows x 2348)  +  gh = W_hh @ h0 (6144 rows x 2048) ----
    for (int w = gw; w < L + G3H; w += NWARP) {
        float acc = 0.f;
        if (w < L) {
            const float4* Wr = attn_W4 + (size_t)w * CAT4;
            const float4* x4 = (const float4*)g_cat1;
#pragma unroll
            for (int k = 0; k < 19; ++k) {
                int idx = k * 32 + lane;
                if (idx < CAT4) {
                    float4 a = Wr[idx], b = x4[idx];
                    acc += a.x * b.x + a.y * b.y + a.z * b.z + a.w * b.w;
                }
            }
            acc = warp_sum(acc);
            if (lane == 0) g_attn_logits[w] = acc + attn_b[w];
        } else {
            int r = w - L;
            const float4* Wr = Whh4 + (size_t)r * H4;
#pragma unroll
            for (int k = 0; k < 16; ++k) {
                int idx = k * 32 + lane;
                float4 a = Wr[idx], b = h04[idx];
                acc += a.x * b.x + a.y * b.y + a.z * b.z + a.w * b.w;
            }
            acc = warp_sum(acc);
            if (lane == 0) g_gh[r] = acc + b_hh[r];
        }
    }
    grid_bar();

    // ---- S2: softmax over 512 attn logits (block 0 only, 2 elems/thread) ----
    if (blockIdx.x == 0) {
        float v0 = g_attn_logits[tid];
        float v1 = g_attn_logits[tid + 256];
        float m = fmaxf(v0, v1);
#pragma unroll
        for (int o = 16; o; o >>= 1) m = fmaxf(m, __shfl_xor_sync(0xffffffffu, m, o));
        if (lane == 0) sA[wid] = m;
        __syncthreads();
        if (wid == 0) {
            float mm = (lane < 8) ? sA[lane] : -INFINITY;
#pragma unroll
            for (int o = 4; o; o >>= 1) mm = fmaxf(mm, __shfl_xor_sync(0xffffffffu, mm, o));
            if (lane == 0) s_bcast = mm;
        }
        __syncthreads();
        float M = s_bcast;
        float p0 = expf(v0 - M), p1 = expf(v1 - M);
        float s = warp_sum(p0 + p1);
        if (lane == 0) sA[wid] = s;
        __syncthreads();
        if (wid == 0) {
            float ss = (lane < 8) ? sA[lane] : 0.f;
#pragma unroll
            for (int o = 4; o; o >>= 1) ss += __shfl_xor_sync(0xffffffffu, ss, o);
            if (lane == 0) s_bcast = ss;
        }
        __syncthreads();
        float inv = 1.f / s_bcast;
        float w0 = p0 * inv, w1 = p1 * inv;
        g_attn_w[tid] = w0;       g_attn_w[tid + 256] = w1;
        out_attn[tid] = w0;       out_attn[tid + 256] = w1;
    }
    grid_bar();

    // ---- S3: attn_applied partials: 16 chunks x 2048 cols ----
    if (gt < AA_NY * H) {
        int col = gt & (H - 1);
        int chunk = gt >> 11;
        int l0 = chunk * AA_CHUNK;
        const float* e = enc + (size_t)l0 * H + col;
        float acc = 0.f;
#pragma unroll
        for (int l = 0; l < AA_CHUNK; ++l) acc += g_attn_w[l0 + l] * e[(size_t)l * H];
        g_ap[chunk * H + col] = acc;
    }
    grid_bar();

    // ---- S4: reduce partials into cat2[E..) ----
    if (gt < H) {
        float a = 0.f;
#pragma unroll
        for (int c = 0; c < AA_NY; ++c) a += g_ap[c * H + gt];
        g_cat2[E + gt] = a;
    }
    grid_bar();

    // ---- S5: combine + relu: 2048 rows x 2348 ----
    for (int w = gw; w < H; w += NWARP) {
        const float4* Wr = comb_W4 + (size_t)w * CAT4;
        const float4* x4 = (const float4*)g_cat2;
        float acc = 0.f;
#pragma unroll
        for (int k = 0; k < 19; ++k) {
            int idx = k * 32 + lane;
            if (idx < CAT4) {
                float4 a = Wr[idx], b = x4[idx];
                acc += a.x * b.x + a.y * b.y + a.z * b.z + a.w * b.w;
            }
        }
        acc = warp_sum(acc);
        if (lane == 0) g_x[w] = fmaxf(acc + comb_b[w], 0.f);
    }
    grid_bar();

    // ---- S6: gi = W_ih @ x : 6144 rows x 2048 ----
    for (int w = gw; w < G3H; w += NWARP) {
        const float4* Wr = Wih4 + (size_t)w * H4;
        const float4* x4 = (const float4*)g_x;
        float acc = 0.f;
#pragma unroll
        for (int k = 0; k < 16; ++k) {
            int idx = k * 32 + lane;
            float4 a = Wr[idx], b = x4[idx];
            acc += a.x * b.x + a.y * b.y + a.z * b.z + a.w * b.w;
        }
        acc = warp_sum(acc);
        if (lane == 0) g_gi[w] = acc + b_ih[w];
    }
    grid_bar();

    // ---- S7: GRU gates -> h_new ----
    if (gt < H) {
        float i_r = g_gi[gt],       i_z = g_gi[H + gt],       i_n = g_gi[2 * H + gt];
        float h_r = g_gh[gt],       h_z = g_gh[H + gt],       h_n = g_gh[2 * H + gt];
        float r = 1.f / (1.f + expf(-(i_r + h_r)));
        float z = 1.f / (1.f + expf(-(i_z + h_z)));
        float n = tanhf(i_n + r * h_n);
        float h = (1.f - z) * n + z * hidden[gt];
        g_hnew[gt] = h;
        out_h[gt]  = h;
    }
    grid_bar();

    // ---- S8: output GEMV 50000 x 2048 with fused online log-sum-exp ----
    {
        const float4* x4 = (const float4*)g_hnew;
        float m = -INFINITY, s = 0.f;
        for (int r = gw; r < V; r += NWARP) {
            const float4* Wr = outW4 + (size_t)r * H4;
            float acc = 0.f;
#pragma unroll
            for (int k = 0; k < 16; ++k) {
                int idx = k * 32 + lane;
                float4 a = Wr[idx], b = x4[idx];
                acc += a.x * b.x + a.y * b.y + a.z * b.z + a.w * b.w;
            }
            acc = warp_sum(acc);
            if (lane == 0) {
                float v = acc + out_b[r];
                g_logits[r] = v;
                float mn = fmaxf(m, v);
                s = s * expf(m - mn) + expf(v - mn);
                m = mn;
            }
        }
        // merge 8 warps -> per-block (m,s)
        if (lane == 0) { sA[wid] = m; sB[wid] = s; }
        __syncthreads();
        if (tid == 0) {
            float M = sA[0], S = sB[0];
#pragma unroll
            for (int i = 1; i < 8; ++i) {
                float m2 = sA[i], s2 = sB[i];
                float MM = fmaxf(M, m2);
                S = S * expf(M - MM) + s2 * expf(m2 - MM);
                M = MM;
            }
            g_pm[blockIdx.x] = M;
            g_ps[blockIdx.x] = S;
        }
    }
    grid_bar();

    // ---- S9: every block reduces the 296 (m,s) partials, then finalizes its slice ----
    {
        float m = -INFINITY, s = 0.f;
        for (int i = tid; i < NB; i += NT) {
            float m2 = g_pm[i], s2 = g_ps[i];
            float M = fmaxf(m, m2);
            s = s * expf(m - M) + s2 * expf(m2 - M);
            m = M;
        }
#pragma unroll
        for (int o = 16; o; o >>= 1) {
            float m2 = __shfl_xor_sync(0xffffffffu, m, o);
            float s2 = __shfl_xor_sync(0xffffffffu, s, o);
            float M = fmaxf(m, m2);
            s = s * expf(m - M) + s2 * expf(m2 - M);
            m = M;
        }
        if (lane == 0) { sA[wid] = m; sB[wid] = s; }
        __syncthreads();
        if (tid == 0) {
            float M = sA[0], S = sB[0];
#pragma unroll
            for (int i = 1; i < 8; ++i) {
                float m2 = sA[i], s2 = sB[i];
                float MM = fmaxf(M, m2);
                S = S * expf(M - MM) + s2 * expf(m2 - MM);
                M = MM;
            }
            s_bcast = M + logf(S);
        }
        __syncthreads();
        float lse = s_bcast;
        if (gt < V) out_logp[gt] = g_logits[gt] - lse;  // NB*NT = 75776 > V
    }
}

// ---------------- launcher: ONE graph node ----------------
extern "C" void kernel_launch(void* const* d_in, const int* in_sizes, int n_in,
                              void* d_out, int out_size) {
    const int*   input  = (const int*)  d_in[0];
    const float* hidden = (const float*)d_in[1];
    const float* enc    = (const float*)d_in[2];
    const float* emb    = (const float*)d_in[3];
    const float* attn_W = (const float*)d_in[4];
    const float* attn_b = (const float*)d_in[5];
    const float* comb_W = (const float*)d_in[6];
    const float* comb_b = (const float*)d_in[7];
    const float* W_ih   = (const float*)d_in[8];
    const float* W_hh   = (const float*)d_in[9];
    const float* b_ih   = (const float*)d_in[10];
    const float* b_hh   = (const float*)d_in[11];
    const float* out_W  = (const float*)d_in[12];
    const float* out_b  = (const float*)d_in[13];

    float* out = (float*)d_out;
    float* out_logp = out;           // [V]
    float* out_h    = out + V;       // [H]
    float* out_attn = out + V + H;   // [L]

    fused_decoder<<<NB, NT>>>(input, hidden, enc, emb,
                              (const float4*)attn_W, attn_b,
                              (const float4*)comb_W, comb_b,
                              (const float4*)W_ih, (const float4*)W_hh,
                              b_ih, b_hh,
                              (const float4*)out_W, out_b,
                              out_logp, out_h, out_attn);
}

// round 16
// speedup vs baseline: 1.1807x; 1.0022x over previous
#include <cuda_runtime.h>
#include <math.h>
#include <stdint.h>

// Problem constants
#define V 50000
#define E 300
#define H 2048
#define L 512
#define CAT (E + H)          // 2348
#define CAT4 587             // float4 per 2348-row
#define E4 75                // float4 in embedded part (300/4)
#define H4 512               // float4 per 2048-row
#define G3H (3 * H)          // 6144

// Launch geometry: 2 CTAs per SM on 148 SMs -> all blocks resident
#define NB 296
#define NT 256
#define NWARP ((NB * NT) / 32)   // 2368

// ---------------- device scratch (allocation-free) ----------------
__device__ float g_attn_logits[L];
__device__ __align__(16) float g_aa[H];       // attn_applied
__device__ __align__(16) float g_x[H];        // relu(comb) output
__device__ float g_gh[G3H];
__device__ float g_gi[G3H];
__device__ __align__(16) float g_hnew[H];
__device__ float g_logits[V];
__device__ float g_pm[NB];
__device__ float g_ps[NB];
__device__ unsigned int g_bar_a;              // monotone arrive counter
__device__ volatile unsigned int g_bar_v;     // monotone release value

// ---------------- fast grid-wide barrier (volatile-load spin) -------------
__device__ __forceinline__ void grid_bar() {
    __syncthreads();
    if (threadIdx.x == 0) {
        __threadfence();
        unsigned int t = atomicAdd(&g_bar_a, 1u) + 1u;
        unsigned int target = ((t + NB - 1u) / NB) * NB;
        if (t == target) {
            __threadfence();
            g_bar_v = target;                 // st.volatile release
        } else {
            while (g_bar_v < target) { }      // ld.volatile poll (L2)
        }
        __threadfence();
    }
    __syncthreads();
}

__device__ __forceinline__ float warp_sum(float a) {
#pragma unroll
    for (int o = 16; o; o >>= 1) a += __shfl_down_sync(0xffffffffu, a, o);
    return a;
}

__global__ void __launch_bounds__(NT, 2)
fused_decoder(const int* __restrict__ input,
              const float* __restrict__ hidden,
              const float* __restrict__ enc,
              const float* __restrict__ emb,
              const float4* __restrict__ attn_W4,
              const float* __restrict__ attn_b,
              const float4* __restrict__ comb_W4,
              const float* __restrict__ comb_b,
              const float4* __restrict__ Wih4,
              const float4* __restrict__ Whh4,
              const float* __restrict__ b_ih,
              const float* __restrict__ b_hh,
              const float4* __restrict__ outW4,
              const float* __restrict__ out_b,
              float* __restrict__ out_logp,
              float* __restrict__ out_h,
              float* __restrict__ out_attn) {
    __shared__ float s_w[L];                  // softmax weights (2KB)
    __shared__ float sA[8];
    __shared__ float sB[8];
    __shared__ float s_bcast;

    const int tid  = threadIdx.x;
    const int lane = tid & 31;
    const int wid  = tid >> 5;
    const int gt   = blockIdx.x * NT + tid;
    const int gw   = gt >> 5;
    const float4* h04     = (const float4*)hidden;
    const float4* embrow4 = (const float4*)(emb + (size_t)input[0] * E);

    // ---- S1: attn logits (512 x 2348, x = [emb|h0] read directly)
    //          + gh = W_hh @ h0 (6144 x 2048) ----
    for (int w = gw; w < L + G3H; w += NWARP) {
        float acc = 0.f;
        if (w < L) {
            const float4* Wr = attn_W4 + (size_t)w * CAT4;
#pragma unroll
            for (int k = 0; k < 19; ++k) {
                int idx = k * 32 + lane;
                if (idx < CAT4) {
                    const float4* xp = (idx < E4) ? (embrow4 + idx) : (h04 + (idx - E4));
                    float4 a = Wr[idx], b = *xp;
                    acc += a.x * b.x + a.y * b.y + a.z * b.z + a.w * b.w;
                }
            }
            acc = warp_sum(acc);
            if (lane == 0) g_attn_logits[w] = acc + attn_b[w];
        } else {
            int r = w - L;
            const float4* Wr = Whh4 + (size_t)r * H4;
#pragma unroll
            for (int k = 0; k < 16; ++k) {
                int idx = k * 32 + lane;
                float4 a = Wr[idx], b = h04[idx];
                acc += a.x * b.x + a.y * b.y + a.z * b.z + a.w * b.w;
            }
            acc = warp_sum(acc);
            if (lane == 0) g_gh[r] = acc + b_hh[r];
        }
    }
    grid_bar();  // B1

    // ---- S2: per-block redundant softmax (into smem) + attn_applied ----
    {
        float v0 = g_attn_logits[tid];
        float v1 = g_attn_logits[tid + 256];
        float m = fmaxf(v0, v1);
#pragma unroll
        for (int o = 16; o; o >>= 1) m = fmaxf(m, __shfl_xor_sync(0xffffffffu, m, o));
        if (lane == 0) sA[wid] = m;
        __syncthreads();
        if (wid == 0) {
            float mm = (lane < 8) ? sA[lane] : -INFINITY;
#pragma unroll
            for (int o = 4; o; o >>= 1) mm = fmaxf(mm, __shfl_xor_sync(0xffffffffu, mm, o));
            if (lane == 0) s_bcast = mm;
        }
        __syncthreads();
        float M = s_bcast;
        float p0 = expf(v0 - M), p1 = expf(v1 - M);
        float s = warp_sum(p0 + p1);
        if (lane == 0) sA[wid] = s;
        __syncthreads();
        if (wid == 0) {
            float ss = (lane < 8) ? sA[lane] : 0.f;
#pragma unroll
            for (int o = 4; o; o >>= 1) ss += __shfl_xor_sync(0xffffffffu, ss, o);
            if (lane == 0) s_bcast = ss;
        }
        __syncthreads();
        float inv = 1.f / s_bcast;
        float w0 = p0 * inv, w1 = p1 * inv;
        s_w[tid] = w0;       s_w[tid + 256] = w1;
        if (blockIdx.x == 0) { out_attn[tid] = w0; out_attn[tid + 256] = w1; }
        __syncthreads();

        // attn_applied: one warp per encoder column, lanes stride L
        if (gw < H) {
            int col = gw;
            float acc = 0.f;
#pragma unroll
            for (int it = 0; it < L / 32; ++it) {
                int l = it * 32 + lane;
                acc += s_w[l] * enc[(size_t)l * H + col];
            }
            acc = warp_sum(acc);
            if (lane == 0) g_aa[col] = acc;
        }
    }
    grid_bar();  // B2

    // ---- S3: combine + relu: 2048 rows x 2348, x = [emb|attn_applied] ----
    {
        const float4* aa4 = (const float4*)g_aa;
        for (int w = gw; w < H; w += NWARP) {
            const float4* Wr = comb_W4 + (size_t)w * CAT4;
            float acc = 0.f;
#pragma unroll
            for (int k = 0; k < 19; ++k) {
                int idx = k * 32 + lane;
                if (idx < CAT4) {
                    const float4* xp = (idx < E4) ? (embrow4 + idx) : (aa4 + (idx - E4));
                    float4 a = Wr[idx], b = *xp;
                    acc += a.x * b.x + a.y * b.y + a.z * b.z + a.w * b.w;
                }
            }
            acc = warp_sum(acc);
            if (lane == 0) g_x[w] = fmaxf(acc + comb_b[w], 0.f);
        }
    }
    grid_bar();  // B3

    // ---- S4: gi = W_ih @ x : 6144 rows x 2048 ----
    for (int w = gw; w < G3H; w += NWARP) {
        const float4* Wr = Wih4 + (size_t)w * H4;
        const float4* x4 = (const float4*)g_x;
        float acc = 0.f;
#pragma unroll
        for (int k = 0; k < 16; ++k) {
            int idx = k * 32 + lane;
            float4 a = Wr[idx], b = x4[idx];
            acc += a.x * b.x + a.y * b.y + a.z * b.z + a.w * b.w;
        }
        acc = warp_sum(acc);
        if (lane == 0) g_gi[w] = acc + b_ih[w];
    }
    grid_bar();  // B4

    // ---- S5: GRU gates -> h_new ----
    if (gt < H) {
        float i_r = g_gi[gt],    i_z = g_gi[H + gt],    i_n = g_gi[2 * H + gt];
        float h_r = g_gh[gt],    h_z = g_gh[H + gt],    h_n = g_gh[2 * H + gt];
        float r = 1.f / (1.f + expf(-(i_r + h_r)));
        float z = 1.f / (1.f + expf(-(i_z + h_z)));
        float n = tanhf(i_n + r * h_n);
        float h = (1.f - z) * n + z * hidden[gt];
        g_hnew[gt] = h;
        out_h[gt]  = h;
    }
    grid_bar();  // B5

    // ---- S6: output GEMV 50000 x 2048 with fused online log-sum-exp ----
    {
        const float4* x4 = (const float4*)g_hnew;
        float m = -INFINITY, s = 0.f;
        for (int r = gw; r < V; r += NWARP) {
            const float4* Wr = outW4 + (size_t)r * H4;
            float acc = 0.f;
#pragma unroll
            for (int k = 0; k < 16; ++k) {
                int idx = k * 32 + lane;
                float4 a = Wr[idx], b = x4[idx];
                acc += a.x * b.x + a.y * b.y + a.z * b.z + a.w * b.w;
            }
            acc = warp_sum(acc);
            if (lane == 0) {
                float v = acc + out_b[r];
                g_logits[r] = v;
                float mn = fmaxf(m, v);
                s = s * expf(m - mn) + expf(v - mn);
                m = mn;
            }
        }
        if (lane == 0) { sA[wid] = m; sB[wid] = s; }
        __syncthreads();
        if (tid == 0) {
            float M = sA[0], S = sB[0];
#pragma unroll
            for (int i = 1; i < 8; ++i) {
                float m2 = sA[i], s2 = sB[i];
                float MM = fmaxf(M, m2);
                S = S * expf(M - MM) + s2 * expf(m2 - MM);
                M = MM;
            }
            g_pm[blockIdx.x] = M;
            g_ps[blockIdx.x] = S;
        }
    }
    grid_bar();  // B6

    // ---- S7: every block reduces 296 (m,s) partials, finalizes its slice ----
    {
        float m = -INFINITY, s = 0.f;
        for (int i = tid; i < NB; i += NT) {
            float m2 = g_pm[i], s2 = g_ps[i];
            float M = fmaxf(m, m2);
            s = s * expf(m - M) + s2 * expf(m2 - M);
            m = M;
        }
#pragma unroll
        for (int o = 16; o; o >>= 1) {
            float m2 = __shfl_xor_sync(0xffffffffu, m, o);
            float s2 = __shfl_xor_sync(0xffffffffu, s, o);
            float M = fmaxf(m, m2);
            s = s * expf(m - M) + s2 * expf(m2 - M);
            m = M;
        }
        if (lane == 0) { sA[wid] = m; sB[wid] = s; }
        __syncthreads();
        if (tid == 0) {
            float M = sA[0], S = sB[0];
#pragma unroll
            for (int i = 1; i < 8; ++i) {
                float m2 = sA[i], s2 = sB[i];
                float MM = fmaxf(M, m2);
                S = S * expf(M - MM) + s2 * expf(m2 - MM);
                M = MM;
            }
            s_bcast = M + logf(S);
        }
        __syncthreads();
        float lse = s_bcast;
        if (gt < V) out_logp[gt] = g_logits[gt] - lse;   // NB*NT = 75776 > V
    }
}

// ---------------- launcher: ONE graph node ----------------
extern "C" void kernel_launch(void* const* d_in, const int* in_sizes, int n_in,
                              void* d_out, int out_size) {
    const int*   input  = (const int*)  d_in[0];
    const float* hidden = (const float*)d_in[1];
    const float* enc    = (const float*)d_in[2];
    const float* emb    = (const float*)d_in[3];
    const float* attn_W = (const float*)d_in[4];
    const float* attn_b = (const float*)d_in[5];
    const float* comb_W = (const float*)d_in[6];
    const float* comb_b = (const float*)d_in[7];
    const float* W_ih   = (const float*)d_in[8];
    const float* W_hh   = (const float*)d_in[9];
    const float* b_ih   = (const float*)d_in[10];
    const float* b_hh   = (const float*)d_in[11];
    const float* out_W  = (const float*)d_in[12];
    const float* out_b  = (const float*)d_in[13];

    float* out = (float*)d_out;
    float* out_logp = out;           // [V]
    float* out_h    = out + V;       // [H]
    float* out_attn = out + V + H;   // [L]

    fused_decoder<<<NB, NT>>>(input, hidden, enc, emb,
                              (const float4*)attn_W, attn_b,
                              (const float4*)comb_W, comb_b,
                              (const float4*)W_ih, (const float4*)W_hh,
                              b_ih, b_hh,
                              (const float4*)out_W, out_b,
                              out_logp, out_h, out_attn);
}